// round 5
// baseline (speedup 1.0000x reference)
#include <cuda_runtime.h>
#include <cuda_fp16.h>
#include <math.h>
#include <float.h>
#include <stdint.h>

#define BATCH 8
#define CH 64
#define NPTS 4096
#define KNN 20
#define CAND 32
#define OC 64
#define NPOINTS (BATCH * NPTS)          // 32768
#define NEG_SLOPE 0.2f
#define BN_EPS 1e-5f

// ---------------- scratch (static device globals; no allocation) ------------
__device__ int   g_cand[NPOINTS * CAND];             // approx top-32 per row
__device__ int   g_idx[NPOINTS * KNN];               // exact top-20 per row
__device__ float g_xt[NPOINTS * CH];                 // x transposed: point-major
__device__ float g_u[NPOINTS * OC];
__device__ float g_v[NPOINTS * OC];
__device__ float g_sq[NPOINTS];
__device__ float g_Mmax[NPOINTS * OC];
__device__ float g_Mmin[NPOINTS * OC];
__device__ float g_partS[8192 * OC];
__device__ float g_partQ[8192 * OC];
__device__ float g_sum[OC];
__device__ float g_sumsq[OC];
__device__ float g_scale[OC];
__device__ float g_shift[OC];

// ---------------- SMEM layout (float word indices) ---------------------------
#define SM_BP    0            // packed fp16 B: 2048 uint2 = 4096 words (16KB)
#define SM_KEYS  4096         // keys 128 x 130 (also A fp32 staging 64 x 130)
#define SM_HSQ   20736        // 4096 words: 0.5*|x_m|^2 whole batch
#define SM_RBEST 24832        // 128 x 33
#define SM_RIDX  29056        // 128 x 33 (int)
#define SM_FLOATS 33280
#define SMEM_BYTES (SM_FLOATS * 4)   // 133120 B
#define KEYP 130
#define RP 33

// ---------------- helpers -----------------------------------------------------
__device__ __forceinline__ uint32_t pack_half2(float lo, float hi) {
    uint32_t d;
    asm("cvt.rn.f16x2.f32 %0, %2, %1;" : "=r"(d) : "f"(lo), "f"(hi));
    return d;
}
__device__ __forceinline__ void mma_fp16(float* d, const uint32_t* a, uint32_t b0, uint32_t b1) {
    asm volatile(
        "mma.sync.aligned.m16n8k16.row.col.f32.f16.f16.f32 "
        "{%0,%1,%2,%3}, {%4,%5,%6,%7}, {%8,%9}, {%0,%1,%2,%3};"
        : "+f"(d[0]), "+f"(d[1]), "+f"(d[2]), "+f"(d[3])
        : "r"(a[0]), "r"(a[1]), "r"(a[2]), "r"(a[3]), "r"(b0), "r"(b1));
}

// ---------------- |x|^2 per point -------------------------------------------
__global__ void sq_kernel(const float* __restrict__ x) {
    int t = blockIdx.x * blockDim.x + threadIdx.x;
    int b = t >> 12, n = t & (NPTS - 1);
    const float* xb = x + (size_t)b * CH * NPTS + n;
    float s = 0.f;
#pragma unroll
    for (int c = 0; c < CH; c++) { float v = xb[(size_t)c * NPTS]; s = fmaf(v, v, s); }
    g_sq[t] = s;
}

// ---------------- u = W1*x, v = (W2-W1)*x; also writes xT --------------------
__global__ void __launch_bounds__(256) uv_kernel(const float* __restrict__ x,
                                                 const float* __restrict__ W) {
    __shared__ float Ws[OC][129];
    __shared__ float xs[4][CH];
    int tid = threadIdx.x;
    for (int t = tid; t < OC * 2 * CH; t += 256) {
        int o = t >> 7, c = t & 127;
        Ws[o][c] = W[t];
    }
    int p4 = blockIdx.x * 4;
    int b = p4 >> 12, n0 = p4 & (NPTS - 1);
    for (int t = tid; t < 4 * CH; t += 256) {
        int c = t >> 2, p = t & 3;
        xs[p][c] = x[(size_t)b * CH * NPTS + (size_t)c * NPTS + n0 + p];
    }
    __syncthreads();
    int o = tid & 63, p = tid >> 6;
    float u = 0.f, v = 0.f;
#pragma unroll
    for (int c = 0; c < CH; c++) {
        float xv = xs[p][c];
        float w1 = Ws[o][c], w2 = Ws[o][CH + c];
        u = fmaf(w1, xv, u);
        v = fmaf(w2 - w1, xv, v);
    }
    size_t base = (size_t)(p4 + p) * OC + o;
    g_u[base] = u;
    g_v[base] = v;
    g_xt[(size_t)(p4 + p) * CH + o] = xs[p][o];
}

// ---------------- fused fp16 approx distance GEMM + top-32 candidates --------
__global__ void __launch_bounds__(256, 1) fused_knn_approx(const float* __restrict__ x) {
    extern __shared__ float sm[];
    int* smi = (int*)sm;
    uint32_t* smB = (uint32_t*)(sm + SM_BP);

    int tid = threadIdx.x;
    int w = tid >> 5, lane = tid & 31;
    int g = lane >> 2, t4 = lane & 3;
    int b = blockIdx.y, n0 = blockIdx.x << 7;
    const float* xb = x + (size_t)b * CH * NPTS;

    for (int t = tid; t < NPTS; t += 256) sm[SM_HSQ + t] = 0.5f * g_sq[(b << 12) + t];
    for (int t = tid; t < 128 * RP; t += 256) { sm[SM_RBEST + t] = -FLT_MAX; smi[SM_RIDX + t] = -1; }

    // ---- stage A tile fp32 into keys region (pitch 130): st[c*130 + r]
    {
        const float* src = xb + n0;
        for (int t = tid; t < CH * 128; t += 256)
            sm[SM_KEYS + (t >> 7) * KEYP + (t & 127)] = src[(size_t)(t >> 7) * NPTS + (t & 127)];
    }
    __syncthreads();

    // ---- A fragments (fp16 packed), warp w owns rows w*16..w*16+15
    uint32_t Af[4][4];
    {
        const float* st = sm + SM_KEYS;
        int r0 = (w << 4) + g, r1 = r0 + 8;
#pragma unroll
        for (int ks = 0; ks < 4; ks++) {
            int kb = ks << 4;
            const float* s0 = st + (kb + 2 * t4) * KEYP;
            const float* s1 = s0 + KEYP;
            const float* s2 = st + (kb + 2 * t4 + 8) * KEYP;
            const float* s3 = s2 + KEYP;
            Af[ks][0] = pack_half2(s0[r0], s1[r0]);
            Af[ks][1] = pack_half2(s0[r1], s1[r1]);
            Af[ks][2] = pack_half2(s2[r0], s3[r0]);
            Af[ks][3] = pack_half2(s2[r1], s3[r1]);
        }
    }
    __syncthreads();   // staging consumed; keys region free

    float worst = -FLT_MAX;
    int wp = 0;
    int rb = (tid & 127) * RP;

    for (int mt = 0; mt < 32; mt++) {
        // ---- selection for previous tile (owners tid<128)
        if (mt > 0 && tid < 128) {
            int m0p = (mt - 1) << 7;
            const float2* krow = (const float2*)(sm + SM_KEYS + tid * KEYP);
#pragma unroll 4
            for (int c2 = 0; c2 < 64; c2++) {
                float2 kk = krow[c2];
                if (kk.x > worst) {
                    sm[SM_RBEST + rb + wp] = kk.x; smi[SM_RIDX + rb + wp] = m0p + 2 * c2;
                    worst = sm[SM_RBEST + rb]; wp = 0;
#pragma unroll
                    for (int t = 1; t < CAND; t++) {
                        float vv = sm[SM_RBEST + rb + t];
                        if (vv < worst) { worst = vv; wp = t; }
                    }
                }
                if (kk.y > worst) {
                    sm[SM_RBEST + rb + wp] = kk.y; smi[SM_RIDX + rb + wp] = m0p + 2 * c2 + 1;
                    worst = sm[SM_RBEST + rb]; wp = 0;
#pragma unroll
                    for (int t = 1; t < CAND; t++) {
                        float vv = sm[SM_RBEST + rb + t];
                        if (vv < worst) { worst = vv; wp = t; }
                    }
                }
            }
        }

        // ---- load + convert + fragment-pack B tile (fp16)
        {
            const float* src = xb + (mt << 7);
#pragma unroll
            for (int it = 0; it < 4; it++) {
                int c = it * 16 + w * 2;           // even channel
                int nn = lane << 2;
                float4 v0 = *(const float4*)(src + (size_t)c * NPTS + nn);
                float4 v1 = *(const float4*)(src + (size_t)(c + 1) * NPTS + nn);
                int ks = c >> 4, r = c & 15;
                int reg = r >> 3, tt = (r & 7) >> 1;
#pragma unroll
                for (int j = 0; j < 4; j++) {
                    int n = nn + j;
                    int gg = n & 7, colt = n >> 3;
                    int lanei = 4 * gg + tt;
                    int idx = ((colt << 2) + ks) * 32 + (lanei ^ (colt << 1));
                    float lo = (&v0.x)[j], hi = (&v1.x)[j];
                    smB[idx * 2 + reg] = pack_half2(lo, hi);
                }
            }
        }
        __syncthreads();   // B ready, prev keys consumed

        // ---- MMA: 16 col-tiles x 4 ksteps, single fp16 product
        float acc[16][4];
#pragma unroll
        for (int ct = 0; ct < 16; ct++) {
            acc[ct][0] = 0.f; acc[ct][1] = 0.f; acc[ct][2] = 0.f; acc[ct][3] = 0.f;
        }
#pragma unroll
        for (int ks = 0; ks < 4; ks++) {
#pragma unroll
            for (int ct = 0; ct < 16; ct++) {
                uint2 bb = *(const uint2*)(smB + (((ct << 2) + ks) * 32 + (lane ^ (ct << 1))) * 2);
                mma_fp16(acc[ct], Af[ks], bb.x, bb.y);
            }
        }

        // ---- epilogue: key = acc - 0.5|x_m|^2 -> keys SMEM
        {
            int m0 = mt << 7;
            int r0 = (w << 4) + g, r1 = r0 + 8;
#pragma unroll
            for (int ct = 0; ct < 16; ct++) {
                int nc = ct * 8 + 2 * t4;
                float2 hs = *(const float2*)(sm + SM_HSQ + m0 + nc);
                float2 k01, k23;
                k01.x = acc[ct][0] - hs.x; k01.y = acc[ct][1] - hs.y;
                k23.x = acc[ct][2] - hs.x; k23.y = acc[ct][3] - hs.y;
                *(float2*)(sm + SM_KEYS + r0 * KEYP + nc) = k01;
                *(float2*)(sm + SM_KEYS + r1 * KEYP + nc) = k23;
            }
        }
        __syncthreads();   // keys(mt) ready
    }

    // ---- final tile selection + candidate output
    if (tid < 128) {
        int m0p = 31 << 7;
        const float2* krow = (const float2*)(sm + SM_KEYS + tid * KEYP);
#pragma unroll 4
        for (int c2 = 0; c2 < 64; c2++) {
            float2 kk = krow[c2];
            if (kk.x > worst) {
                sm[SM_RBEST + rb + wp] = kk.x; smi[SM_RIDX + rb + wp] = m0p + 2 * c2;
                worst = sm[SM_RBEST + rb]; wp = 0;
#pragma unroll
                for (int t = 1; t < CAND; t++) {
                    float vv = sm[SM_RBEST + rb + t];
                    if (vv < worst) { worst = vv; wp = t; }
                }
            }
            if (kk.y > worst) {
                sm[SM_RBEST + rb + wp] = kk.y; smi[SM_RIDX + rb + wp] = m0p + 2 * c2 + 1;
                worst = sm[SM_RBEST + rb]; wp = 0;
#pragma unroll
                for (int t = 1; t < CAND; t++) {
                    float vv = sm[SM_RBEST + rb + t];
                    if (vv < worst) { worst = vv; wp = t; }
                }
            }
        }
        int* outp = g_cand + (size_t)((b << 12) + n0 + tid) * CAND;
#pragma unroll
        for (int t = 0; t < CAND; t++) outp[t] = smi[SM_RIDX + rb + t];
    }
}

// ---------------- exact fp32 rescore of 32 candidates -> top-20 --------------
__global__ void __launch_bounds__(256) rescore_kernel() {
    __shared__ float rowbuf[8][CH];
    int w = threadIdx.x >> 5, lane = threadIdx.x & 31;
    int row = blockIdx.x * 8 + w;
    int b = row >> 12;

    // own point into smem (warp-local)
    float2 me = *(const float2*)(g_xt + (size_t)row * CH + lane * 2);
    rowbuf[w][lane * 2] = me.x;
    rowbuf[w][lane * 2 + 1] = me.y;
    __syncwarp();

    int cand = g_cand[(size_t)row * CAND + lane];
    const float4* cp = (const float4*)(g_xt + ((size_t)(b << 12) + cand) * CH);
    float dot = 0.f;
#pragma unroll
    for (int i = 0; i < 16; i++) {
        float4 v = cp[i];
        dot = fmaf(v.x, rowbuf[w][4 * i + 0], dot);
        dot = fmaf(v.y, rowbuf[w][4 * i + 1], dot);
        dot = fmaf(v.z, rowbuf[w][4 * i + 2], dot);
        dot = fmaf(v.w, rowbuf[w][4 * i + 3], dot);
    }
    float key = fmaf(2.f, dot, -g_sq[(b << 12) + cand]);

    int* outp = g_idx + (size_t)row * KNN;
#pragma unroll
    for (int r = 0; r < KNN; r++) {
        float bk = key; int bi = (key == -FLT_MAX) ? 0x7fffffff : cand;
#pragma unroll
        for (int off = 16; off > 0; off >>= 1) {
            float ok = __shfl_down_sync(0xffffffffu, bk, off);
            int   oi = __shfl_down_sync(0xffffffffu, bi, off);
            if (ok > bk || (ok == bk && oi < bi)) { bk = ok; bi = oi; }
        }
        bi = __shfl_sync(0xffffffffu, bi, 0);
        if (lane == 0) outp[r] = bi;
        if (cand == bi) key = -FLT_MAX;
    }
}

// ---------------- gather u over neighbors: max/min + BN partials ------------
__global__ void __launch_bounds__(256) gather_kernel() {
    __shared__ float shS[4][OC];
    __shared__ float shQ[4][OC];
    int o = threadIdx.x & 63, p = threadIdx.x >> 6;
    int pt = blockIdx.x * 4 + p;
    int b = pt >> 12;
    const int* idxp = g_idx + (size_t)pt * KNN;
    const float* ub = g_u + ((size_t)(b << 12)) * OC;

    float mx = -FLT_MAX, mn = FLT_MAX, s = 0.f, q = 0.f;
#pragma unroll
    for (int k = 0; k < KNN; k++) {
        int j = idxp[k];
        float uv = ub[(size_t)j * OC + o];
        mx = fmaxf(mx, uv);
        mn = fminf(mn, uv);
        s += uv;
        q = fmaf(uv, uv, q);
    }
    size_t base = (size_t)pt * OC + o;
    float vv = g_v[base];
    g_Mmax[base] = mx;
    g_Mmin[base] = mn;
    shS[p][o] = s + (float)KNN * vv;
    shQ[p][o] = q + 2.f * vv * s + (float)KNN * vv * vv;
    __syncthreads();
    if (p == 0) {
        g_partS[blockIdx.x * OC + o] = shS[0][o] + shS[1][o] + shS[2][o] + shS[3][o];
        g_partQ[blockIdx.x * OC + o] = shQ[0][o] + shQ[1][o] + shQ[2][o] + shQ[3][o];
    }
}

// ---------------- deterministic per-channel reduction ------------------------
__global__ void reduce_kernel() {
    __shared__ float sh[256];
    int o = blockIdx.x & 63;
    bool isQ = (blockIdx.x & 64) != 0;
    const float* src = isQ ? g_partQ : g_partS;
    float s = 0.f;
    for (int i = threadIdx.x; i < 8192; i += 256) s += src[(size_t)i * OC + o];
    sh[threadIdx.x] = s;
    __syncthreads();
    for (int st = 128; st > 0; st >>= 1) {
        if (threadIdx.x < st) sh[threadIdx.x] += sh[threadIdx.x + st];
        __syncthreads();
    }
    if (threadIdx.x == 0) {
        if (isQ) g_sumsq[o] = sh[0]; else g_sum[o] = sh[0];
    }
}

__global__ void finalize_kernel(const float* __restrict__ gamma,
                                const float* __restrict__ beta) {
    int o = threadIdx.x;
    float cnt = (float)((size_t)BATCH * NPTS * KNN);
    float mean = g_sum[o] / cnt;
    float var = g_sumsq[o] / cnt - mean * mean;
    float sc = gamma[o] * rsqrtf(var + BN_EPS);
    g_scale[o] = sc;
    g_shift[o] = beta[o] - mean * sc;
}

// ---------------- output: scale/shift/leaky + transpose to [B, O, N] --------
__global__ void __launch_bounds__(256) out_kernel(float* __restrict__ out) {
    __shared__ float tile[OC][33];
    int b = blockIdx.y;
    int n0 = blockIdx.x * 32;
    for (int t = threadIdx.x; t < OC * 32; t += 256) {
        int nl = t >> 6, o = t & 63;
        size_t base = ((size_t)((b << 12) + n0 + nl)) * OC + o;
        float sc = g_scale[o];
        float m = (sc >= 0.f) ? g_Mmax[base] : g_Mmin[base];
        float y = fmaf(sc, m + g_v[base], g_shift[o]);
        tile[o][nl] = (y >= 0.f) ? y : NEG_SLOPE * y;
    }
    __syncthreads();
    for (int t = threadIdx.x; t < OC * 32; t += 256) {
        int o = t >> 5, nl = t & 31;
        out[((size_t)b * OC + o) * NPTS + n0 + nl] = tile[o][nl];
    }
}

// ---------------- launch ------------------------------------------------------
extern "C" void kernel_launch(void* const* d_in, const int* in_sizes, int n_in,
                              void* d_out, int out_size) {
    const float* x     = (const float*)d_in[0];   // [8, 64, 4096]
    const float* W     = (const float*)d_in[1];   // [64, 128]
    const float* gamma = (const float*)d_in[2];   // [64]
    const float* beta  = (const float*)d_in[3];   // [64]
    float* out = (float*)d_out;                   // [8, 64, 4096]

    cudaFuncSetAttribute(fused_knn_approx,
                         cudaFuncAttributeMaxDynamicSharedMemorySize, SMEM_BYTES);

    sq_kernel<<<NPOINTS / 256, 256>>>(x);
    uv_kernel<<<NPOINTS / 4, 256>>>(x, W);
    fused_knn_approx<<<dim3(NPTS / 128, BATCH), 256, SMEM_BYTES>>>(x);
    rescore_kernel<<<NPOINTS / 8, 256>>>();
    gather_kernel<<<NPOINTS / 4, 256>>>();
    reduce_kernel<<<128, 256>>>();
    finalize_kernel<<<1, 64>>>(gamma, beta);
    out_kernel<<<dim3(NPTS / 32, BATCH), 256>>>(out);
}

// round 8
// speedup vs baseline: 1.6188x; 1.6188x over previous
#include <cuda_runtime.h>
#include <cuda_fp16.h>
#include <math.h>
#include <float.h>
#include <stdint.h>

#define BATCH 8
#define CH 64
#define NPTS 4096
#define KNN 20
#define CAND 32
#define OC 64
#define NPOINTS (BATCH * NPTS)          // 32768
#define NEG_SLOPE 0.2f
#define BN_EPS 1e-5f

// ---------------- scratch (static device globals; no allocation) ------------
__device__ uint4 g_ap[BATCH * 256 * 4 * 32];            // A-frag pack (4MB)
__device__ uint2 g_bp[BATCH * 512 * 4 * 32];            // B-frag pack (4MB)
__device__ int   g_cand[NPOINTS * CAND];
__device__ int   g_idx[NPOINTS * KNN];
__device__ float g_xt[NPOINTS * CH];
__device__ float g_u[NPOINTS * OC];
__device__ float g_v[NPOINTS * OC];
__device__ float g_sq[NPOINTS];
__device__ float g_Mmax[NPOINTS * OC];
__device__ float g_Mmin[NPOINTS * OC];
__device__ float g_partS[8192 * OC];
__device__ float g_partQ[8192 * OC];
__device__ float g_sum[OC];
__device__ float g_sumsq[OC];
__device__ float g_scale[OC];
__device__ float g_shift[OC];

// ---------------- SMEM layout of fused kernel (word indices) ----------------
#define SM_HSQ   0          // 4224 words: hsq (4096) / merge scratch (128*33)
#define SM_LIST  4224       // 40 * 256 = 10240 words (per-thread top-20 x 2 rows)
#define SM_WORDS 14464
#define SMEM_BYTES (SM_WORDS * 4)   // 57856 B

// encoded value of -FLT_MAX (list init): decodes back to -FLT_MAX exactly
#define ENC_NEGMAX 0x00800000u

// ---------------- helpers -----------------------------------------------------
__device__ __forceinline__ uint32_t pack_half2(float lo, float hi) {
    uint32_t d;
    asm("cvt.rn.f16x2.f32 %0, %2, %1;" : "=r"(d) : "f"(lo), "f"(hi));
    return d;
}
__device__ __forceinline__ void mma_fp16(float* d, const uint32_t* a, uint32_t b0, uint32_t b1) {
    asm volatile(
        "mma.sync.aligned.m16n8k16.row.col.f32.f16.f16.f32 "
        "{%0,%1,%2,%3}, {%4,%5,%6,%7}, {%8,%9}, {%0,%1,%2,%3};"
        : "+f"(d[0]), "+f"(d[1]), "+f"(d[2]), "+f"(d[3])
        : "r"(a[0]), "r"(a[1]), "r"(a[2]), "r"(a[3]), "r"(b0), "r"(b1));
}
// order-preserving float->uint, top 20 bits kept, 12-bit column index appended
__device__ __forceinline__ uint32_t enc_key(float k, int m) {
    uint32_t u = __float_as_uint(k);
    u ^= (uint32_t)(((int)u >> 31)) | 0x80000000u;
    return (u & 0xFFFFF000u) | (uint32_t)m;
}
// insert entry into per-thread SMEM list (stride 256), refresh min slot + float threshold
__device__ __forceinline__ void ins20(uint32_t* lb, uint32_t e, float& worst, int& wp) {
    lb[wp << 8] = e;
    uint32_t mn = lb[0]; int p = 0;
#pragma unroll
    for (int t = 1; t < 20; t++) {
        uint32_t v = lb[t << 8];
        if (v < mn) { mn = v; p = t; }
    }
    wp = p;
    uint32_t eb = mn & 0xFFFFF000u;
    uint32_t dm = (eb & 0x80000000u) ? 0x80000000u : 0xFFFFFFFFu;
    worst = __uint_as_float(eb ^ dm);
}

// ---------------- |x|^2 per point -------------------------------------------
__global__ void sq_kernel(const float* __restrict__ x) {
    int t = blockIdx.x * blockDim.x + threadIdx.x;
    int b = t >> 12, n = t & (NPTS - 1);
    const float* xb = x + (size_t)b * CH * NPTS + n;
    float s = 0.f;
#pragma unroll
    for (int c = 0; c < CH; c++) { float v = xb[(size_t)c * NPTS]; s = fmaf(v, v, s); }
    g_sq[t] = s;
}

// ---------------- fragment pre-pack kernels ----------------------------------
__global__ void __launch_bounds__(256) apack_kernel(const float* __restrict__ x) {
    int t = blockIdx.x * 256 + threadIdx.x;          // 0..262143
    int lane = t & 31, ks = (t >> 5) & 3, wt = (t >> 7) & 255, b = t >> 15;
    int g = lane >> 2, t4 = lane & 3;
    int r0 = (wt << 4) + g;
    int k0 = (ks << 4) + 2 * t4;
    const float* xb = x + (size_t)b * CH * NPTS;
    uint4 o;
    o.x = pack_half2(xb[(size_t)k0 * NPTS + r0],           xb[(size_t)(k0 + 1) * NPTS + r0]);
    o.y = pack_half2(xb[(size_t)k0 * NPTS + r0 + 8],       xb[(size_t)(k0 + 1) * NPTS + r0 + 8]);
    o.z = pack_half2(xb[(size_t)(k0 + 8) * NPTS + r0],     xb[(size_t)(k0 + 9) * NPTS + r0]);
    o.w = pack_half2(xb[(size_t)(k0 + 8) * NPTS + r0 + 8], xb[(size_t)(k0 + 9) * NPTS + r0 + 8]);
    g_ap[t] = o;
}
__global__ void __launch_bounds__(256) bpack_kernel(const float* __restrict__ x) {
    int t = blockIdx.x * 256 + threadIdx.x;          // 0..524287
    int lane = t & 31, ks = (t >> 5) & 3, ct = (t >> 7) & 511, b = t >> 16;
    int n = (ct << 3) + (lane >> 2);
    int k0 = (ks << 4) + 2 * (lane & 3);
    const float* xb = x + (size_t)b * CH * NPTS;
    uint2 o;
    o.x = pack_half2(xb[(size_t)k0 * NPTS + n],       xb[(size_t)(k0 + 1) * NPTS + n]);
    o.y = pack_half2(xb[(size_t)(k0 + 8) * NPTS + n], xb[(size_t)(k0 + 9) * NPTS + n]);
    g_bp[t] = o;
}

// ---------------- u = W1*x, v = (W2-W1)*x; also writes xT --------------------
__global__ void __launch_bounds__(256) uv_kernel(const float* __restrict__ x,
                                                 const float* __restrict__ W) {
    __shared__ float Ws[OC][129];
    __shared__ float xs[4][CH];
    int tid = threadIdx.x;
    for (int t = tid; t < OC * 2 * CH; t += 256) {
        int o = t >> 7, c = t & 127;
        Ws[o][c] = W[t];
    }
    int p4 = blockIdx.x * 4;
    int b = p4 >> 12, n0 = p4 & (NPTS - 1);
    for (int t = tid; t < 4 * CH; t += 256) {
        int c = t >> 2, p = t & 3;
        xs[p][c] = x[(size_t)b * CH * NPTS + (size_t)c * NPTS + n0 + p];
    }
    __syncthreads();
    int o = tid & 63, p = tid >> 6;
    float u = 0.f, v = 0.f;
#pragma unroll
    for (int c = 0; c < CH; c++) {
        float xv = xs[p][c];
        float w1 = Ws[o][c], w2 = Ws[o][CH + c];
        u = fmaf(w1, xv, u);
        v = fmaf(w2 - w1, xv, v);
    }
    size_t base = (size_t)(p4 + p) * OC + o;
    g_u[base] = u;
    g_v[base] = v;
    g_xt[(size_t)(p4 + p) * CH + o] = xs[p][o];
}

// ---------------- fused fp16 distance MMA + register-side top-20 ------------
__global__ void __launch_bounds__(256, 2) fused_knn(const float* __restrict__ x) {
    extern __shared__ float smf[];
    uint32_t* smu = (uint32_t*)smf;

    int tid = threadIdx.x;
    int w = tid >> 5, lane = tid & 31;
    int t4 = lane & 3;
    int b = blockIdx.y, n0 = blockIdx.x << 7;

    // hsq preload (whole batch)
    for (int t = tid; t < NPTS; t += 256) smf[SM_HSQ + t] = 0.5f * g_sq[(b << 12) + t];
    // list init: encoded(-FLT_MAX) so the decoded threshold is a real float
    {
        uint32_t* lb = smu + SM_LIST + tid;
#pragma unroll
        for (int e = 0; e < 40; e++) lb[e << 8] = ENC_NEGMAX;
    }
    // A fragments (16 rows per warp) from pre-pack
    uint32_t Afr[4][4];
    {
        int wt = blockIdx.x * 8 + w;
#pragma unroll
        for (int ks = 0; ks < 4; ks++) {
            uint4 a = __ldg(&g_ap[((b * 256 + wt) * 4 + ks) * 32 + lane]);
            Afr[ks][0] = a.x; Afr[ks][1] = a.y; Afr[ks][2] = a.z; Afr[ks][3] = a.w;
        }
    }
    __syncthreads();

    uint32_t* lb0 = smu + SM_LIST + tid;
    uint32_t* lb1 = lb0 + 20 * 256;
    float worst0 = -FLT_MAX, worst1 = -FLT_MAX;
    int wp0 = 0, wp1 = 0;

    for (int mt = 0; mt < 32; mt++) {
        const uint2* bp = g_bp + (size_t)((b * 512 + (mt << 4)) * 4) * 32 + lane;
#pragma unroll 4
        for (int ct = 0; ct < 16; ct++) {
            uint2 b0 = __ldg(bp + (ct * 4 + 0) * 32);
            uint2 b1 = __ldg(bp + (ct * 4 + 1) * 32);
            uint2 b2 = __ldg(bp + (ct * 4 + 2) * 32);
            uint2 b3 = __ldg(bp + (ct * 4 + 3) * 32);
            float a4[4] = {0.f, 0.f, 0.f, 0.f};
            mma_fp16(a4, Afr[0], b0.x, b0.y);
            mma_fp16(a4, Afr[1], b1.x, b1.y);
            mma_fp16(a4, Afr[2], b2.x, b2.y);
            mma_fp16(a4, Afr[3], b3.x, b3.y);

            int m = (mt << 7) + (ct << 3) + 2 * t4;
            float2 hs = *(const float2*)(smf + SM_HSQ + m);
            float k0 = a4[0] - hs.x, k1 = a4[1] - hs.y;    // row r0
            float k2 = a4[2] - hs.x, k3 = a4[3] - hs.y;    // row r1
            if (k0 > worst0) ins20(lb0, enc_key(k0, m),     worst0, wp0);
            if (k1 > worst0) ins20(lb0, enc_key(k1, m + 1), worst0, wp0);
            if (k2 > worst1) ins20(lb1, enc_key(k2, m),     worst1, wp1);
            if (k3 > worst1) ins20(lb1, enc_key(k3, m + 1), worst1, wp1);
        }
    }
    __syncthreads();

    // merge 4 x top-20 -> top-32 candidates per row (owner thread per row)
    if (tid < 128) {
        int w2 = tid >> 4, gg = tid & 15;
        uint32_t* lst = smu + SM_LIST + ((gg < 8) ? 0 : 20 * 256) + w2 * 32 + ((gg & 7) << 2);
        uint32_t* scr = smu + SM_HSQ + tid * 33;   // reuse hsq region, pitch 33
#pragma unroll
        for (int s = 0; s < 32; s++) scr[s] = 0u;
        uint32_t wE = 0u; int wp = 0;
        for (int q = 0; q < 4; q++) {
#pragma unroll
            for (int e = 0; e < 20; e++) {
                uint32_t v = lst[(e << 8) + q];
                if (v > wE) {
                    scr[wp] = v;
                    uint32_t mn = scr[0]; int p = 0;
#pragma unroll
                    for (int s2 = 1; s2 < 32; s2++) {
                        uint32_t vv = scr[s2];
                        if (vv < mn) { mn = vv; p = s2; }
                    }
                    wp = p; wE = mn;
                }
            }
        }
        int* outp = g_cand + (size_t)((b << 12) + n0 + tid) * CAND;
#pragma unroll
        for (int s = 0; s < 32; s++) outp[s] = (int)(scr[s] & 0xFFFu);
    }
}

// ---------------- exact fp32 rescore of 32 candidates -> top-20 --------------
__global__ void __launch_bounds__(256) rescore_kernel() {
    __shared__ float rowbuf[8][CH];
    int w = threadIdx.x >> 5, lane = threadIdx.x & 31;
    int row = blockIdx.x * 8 + w;
    int b = row >> 12;

    float2 me = *(const float2*)(g_xt + (size_t)row * CH + lane * 2);
    rowbuf[w][lane * 2] = me.x;
    rowbuf[w][lane * 2 + 1] = me.y;
    __syncwarp();

    int cand = g_cand[(size_t)row * CAND + lane] & (NPTS - 1);
    const float4* cp = (const float4*)(g_xt + ((size_t)(b << 12) + cand) * CH);
    float dot = 0.f;
#pragma unroll
    for (int i = 0; i < 16; i++) {
        float4 v = cp[i];
        dot = fmaf(v.x, rowbuf[w][4 * i + 0], dot);
        dot = fmaf(v.y, rowbuf[w][4 * i + 1], dot);
        dot = fmaf(v.z, rowbuf[w][4 * i + 2], dot);
        dot = fmaf(v.w, rowbuf[w][4 * i + 3], dot);
    }
    float key = fmaf(2.f, dot, -g_sq[(b << 12) + cand]);

    int* outp = g_idx + (size_t)row * KNN;
#pragma unroll
    for (int r = 0; r < KNN; r++) {
        float bk = key; int bi = (key == -FLT_MAX) ? 0x7fffffff : cand;
#pragma unroll
        for (int off = 16; off > 0; off >>= 1) {
            float ok = __shfl_down_sync(0xffffffffu, bk, off);
            int   oi = __shfl_down_sync(0xffffffffu, bi, off);
            if (ok > bk || (ok == bk && oi < bi)) { bk = ok; bi = oi; }
        }
        bi = __shfl_sync(0xffffffffu, bi, 0);
        if (lane == 0) outp[r] = (bi == 0x7fffffff) ? 0 : bi;   // sentinel guard
        if (cand == bi) key = -FLT_MAX;
    }
}

// ---------------- gather u over neighbors: max/min + BN partials ------------
__global__ void __launch_bounds__(256) gather_kernel() {
    __shared__ float shS[4][OC];
    __shared__ float shQ[4][OC];
    int o = threadIdx.x & 63, p = threadIdx.x >> 6;
    int pt = blockIdx.x * 4 + p;
    int b = pt >> 12;
    const int* idxp = g_idx + (size_t)pt * KNN;
    const float* ub = g_u + ((size_t)(b << 12)) * OC;

    float mx = -FLT_MAX, mn = FLT_MAX, s = 0.f, q = 0.f;
#pragma unroll
    for (int k = 0; k < KNN; k++) {
        int j = idxp[k] & (NPTS - 1);   // safety clamp
        float uv = ub[(size_t)j * OC + o];
        mx = fmaxf(mx, uv);
        mn = fminf(mn, uv);
        s += uv;
        q = fmaf(uv, uv, q);
    }
    size_t base = (size_t)pt * OC + o;
    float vv = g_v[base];
    g_Mmax[base] = mx;
    g_Mmin[base] = mn;
    shS[p][o] = s + (float)KNN * vv;
    shQ[p][o] = q + 2.f * vv * s + (float)KNN * vv * vv;
    __syncthreads();
    if (p == 0) {
        g_partS[blockIdx.x * OC + o] = shS[0][o] + shS[1][o] + shS[2][o] + shS[3][o];
        g_partQ[blockIdx.x * OC + o] = shQ[0][o] + shQ[1][o] + shQ[2][o] + shQ[3][o];
    }
}

// ---------------- deterministic per-channel reduction ------------------------
__global__ void reduce_kernel() {
    __shared__ float sh[256];
    int o = blockIdx.x & 63;
    bool isQ = (blockIdx.x & 64) != 0;
    const float* src = isQ ? g_partQ : g_partS;
    float s = 0.f;
    for (int i = threadIdx.x; i < 8192; i += 256) s += src[(size_t)i * OC + o];
    sh[threadIdx.x] = s;
    __syncthreads();
    for (int st = 128; st > 0; st >>= 1) {
        if (threadIdx.x < st) sh[threadIdx.x] += sh[threadIdx.x + st];
        __syncthreads();
    }
    if (threadIdx.x == 0) {
        if (isQ) g_sumsq[o] = sh[0]; else g_sum[o] = sh[0];
    }
}

__global__ void finalize_kernel(const float* __restrict__ gamma,
                                const float* __restrict__ beta) {
    int o = threadIdx.x;
    float cnt = (float)((size_t)BATCH * NPTS * KNN);
    float mean = g_sum[o] / cnt;
    float var = g_sumsq[o] / cnt - mean * mean;
    float sc = gamma[o] * rsqrtf(var + BN_EPS);
    g_scale[o] = sc;
    g_shift[o] = beta[o] - mean * sc;
}

// ---------------- output: scale/shift/leaky + transpose to [B, O, N] --------
__global__ void __launch_bounds__(256) out_kernel(float* __restrict__ out) {
    __shared__ float tile[OC][33];
    int b = blockIdx.y;
    int n0 = blockIdx.x * 32;
    for (int t = threadIdx.x; t < OC * 32; t += 256) {
        int nl = t >> 6, o = t & 63;
        size_t base = ((size_t)((b << 12) + n0 + nl)) * OC + o;
        float sc = g_scale[o];
        float m = (sc >= 0.f) ? g_Mmax[base] : g_Mmin[base];
        float y = fmaf(sc, m + g_v[base], g_shift[o]);
        tile[o][nl] = (y >= 0.f) ? y : NEG_SLOPE * y;
    }
    __syncthreads();
    for (int t = threadIdx.x; t < OC * 32; t += 256) {
        int o = t >> 5, nl = t & 31;
        out[((size_t)b * OC + o) * NPTS + n0 + nl] = tile[o][nl];
    }
}

// ---------------- launch ------------------------------------------------------
extern "C" void kernel_launch(void* const* d_in, const int* in_sizes, int n_in,
                              void* d_out, int out_size) {
    const float* x     = (const float*)d_in[0];   // [8, 64, 4096]
    const float* W     = (const float*)d_in[1];   // [64, 128]
    const float* gamma = (const float*)d_in[2];   // [64]
    const float* beta  = (const float*)d_in[3];   // [64]
    float* out = (float*)d_out;                   // [8, 64, 4096]

    cudaFuncSetAttribute(fused_knn,
                         cudaFuncAttributeMaxDynamicSharedMemorySize, SMEM_BYTES);

    sq_kernel<<<NPOINTS / 256, 256>>>(x);
    apack_kernel<<<1024, 256>>>(x);
    bpack_kernel<<<2048, 256>>>(x);
    uv_kernel<<<NPOINTS / 4, 256>>>(x, W);
    fused_knn<<<dim3(NPTS / 128, BATCH), 256, SMEM_BYTES>>>(x);
    rescore_kernel<<<NPOINTS / 8, 256>>>();
    gather_kernel<<<NPOINTS / 4, 256>>>();
    reduce_kernel<<<128, 256>>>();
    finalize_kernel<<<1, 64>>>(gamma, beta);
    out_kernel<<<dim3(NPTS / 32, BATCH), 256>>>(out);
}

// round 11
// speedup vs baseline: 1.7400x; 1.0748x over previous
#include <cuda_runtime.h>
#include <cuda_fp16.h>
#include <math.h>
#include <float.h>
#include <stdint.h>

#define BATCH 8
#define CH 64
#define NPTS 4096
#define KNN 20
#define CAND 32
#define OC 64
#define NPOINTS (BATCH * NPTS)          // 32768
#define NEG_SLOPE 0.2f
#define BN_EPS 1e-5f

// ---------------- scratch (static device globals; no allocation) ------------
__device__ uint4 g_ap[BATCH * 256 * 4 * 32];            // A-frag pack (4MB)
__device__ uint2 g_bp[BATCH * 512 * 4 * 32];            // B-frag pack (4MB)
__device__ int   g_cand[NPOINTS * CAND];
__device__ int   g_idx[NPOINTS * KNN];
__device__ float g_xt[NPOINTS * CH];
__device__ float g_u[NPOINTS * OC];
__device__ float g_v[NPOINTS * OC];
__device__ float g_sq[NPOINTS];
__device__ float g_Mmax[NPOINTS * OC];
__device__ float g_Mmin[NPOINTS * OC];
__device__ float g_partS[8192 * OC];
__device__ float g_partQ[8192 * OC];
__device__ float g_sum[OC];
__device__ float g_sumsq[OC];
__device__ float g_scale[OC];
__device__ float g_shift[OC];

// ---------------- SMEM layout of fused kernel (word indices) ----------------
#define SM_HSQ   0          // 4224 words: hsq (4096) / merge scratch (128*33)
#define SM_LIST  4224       // 40 * 256 = 10240 words (per-thread top-20 x 2 rows)
#define SM_WORDS 14464
#define SMEM_BYTES (SM_WORDS * 4)   // 57856 B

// encoded value of -FLT_MAX (list init): decodes back to -FLT_MAX exactly
#define ENC_NEGMAX 0x00800000u

// ---------------- helpers -----------------------------------------------------
__device__ __forceinline__ uint32_t pack_half2(float lo, float hi) {
    uint32_t d;
    asm("cvt.rn.f16x2.f32 %0, %2, %1;" : "=r"(d) : "f"(lo), "f"(hi));
    return d;
}
// fp16-accumulator MMA: d packed as {c0,c1},{c2,c3} half2 regs
__device__ __forceinline__ void mma_fp16a(uint32_t& c0, uint32_t& c1,
                                          const uint32_t* a, uint32_t b0, uint32_t b1) {
    asm volatile(
        "mma.sync.aligned.m16n8k16.row.col.f16.f16.f16.f16 "
        "{%0,%1}, {%2,%3,%4,%5}, {%6,%7}, {%0,%1};"
        : "+r"(c0), "+r"(c1)
        : "r"(a[0]), "r"(a[1]), "r"(a[2]), "r"(a[3]), "r"(b0), "r"(b1));
}
// order-preserving float->uint, top 20 bits kept, 12-bit column index appended
__device__ __forceinline__ uint32_t enc_key(float k, int m) {
    uint32_t u = __float_as_uint(k);
    u ^= (uint32_t)(((int)u >> 31)) | 0x80000000u;
    return (u & 0xFFFFF000u) | (uint32_t)m;
}
// insert entry into per-thread SMEM list (stride 256), refresh min slot + float threshold
__device__ __forceinline__ void ins20(uint32_t* lb, uint32_t e, float& worst, int& wp) {
    lb[wp << 8] = e;
    uint32_t mn = lb[0]; int p = 0;
#pragma unroll
    for (int t = 1; t < 20; t++) {
        uint32_t v = lb[t << 8];
        if (v < mn) { mn = v; p = t; }
    }
    wp = p;
    uint32_t eb = mn & 0xFFFFF000u;
    uint32_t dm = (eb & 0x80000000u) ? 0x80000000u : 0xFFFFFFFFu;
    worst = __uint_as_float(eb ^ dm);
}

// ---------------- |x|^2 per point -------------------------------------------
__global__ void sq_kernel(const float* __restrict__ x) {
    int t = blockIdx.x * blockDim.x + threadIdx.x;
    int b = t >> 12, n = t & (NPTS - 1);
    const float* xb = x + (size_t)b * CH * NPTS + n;
    float s = 0.f;
#pragma unroll
    for (int c = 0; c < CH; c++) { float v = xb[(size_t)c * NPTS]; s = fmaf(v, v, s); }
    g_sq[t] = s;
}

// ---------------- fragment pre-pack kernels ----------------------------------
__global__ void __launch_bounds__(256) apack_kernel(const float* __restrict__ x) {
    int t = blockIdx.x * 256 + threadIdx.x;          // 0..262143
    int lane = t & 31, ks = (t >> 5) & 3, wt = (t >> 7) & 255, b = t >> 15;
    int g = lane >> 2, t4 = lane & 3;
    int r0 = (wt << 4) + g;
    int k0 = (ks << 4) + 2 * t4;
    const float* xb = x + (size_t)b * CH * NPTS;
    uint4 o;
    o.x = pack_half2(xb[(size_t)k0 * NPTS + r0],           xb[(size_t)(k0 + 1) * NPTS + r0]);
    o.y = pack_half2(xb[(size_t)k0 * NPTS + r0 + 8],       xb[(size_t)(k0 + 1) * NPTS + r0 + 8]);
    o.z = pack_half2(xb[(size_t)(k0 + 8) * NPTS + r0],     xb[(size_t)(k0 + 9) * NPTS + r0]);
    o.w = pack_half2(xb[(size_t)(k0 + 8) * NPTS + r0 + 8], xb[(size_t)(k0 + 9) * NPTS + r0 + 8]);
    g_ap[t] = o;
}
__global__ void __launch_bounds__(256) bpack_kernel(const float* __restrict__ x) {
    int t = blockIdx.x * 256 + threadIdx.x;          // 0..524287
    int lane = t & 31, ks = (t >> 5) & 3, ct = (t >> 7) & 511, b = t >> 16;
    int n = (ct << 3) + (lane >> 2);
    int k0 = (ks << 4) + 2 * (lane & 3);
    const float* xb = x + (size_t)b * CH * NPTS;
    uint2 o;
    o.x = pack_half2(xb[(size_t)k0 * NPTS + n],       xb[(size_t)(k0 + 1) * NPTS + n]);
    o.y = pack_half2(xb[(size_t)(k0 + 8) * NPTS + n], xb[(size_t)(k0 + 9) * NPTS + n]);
    g_bp[t] = o;
}

// ---------------- u = W1*x, v = (W2-W1)*x; also writes xT --------------------
// 16 points per block: 4x fewer W reloads, weights reused across 4 points/thread
__global__ void __launch_bounds__(256) uv_kernel(const float* __restrict__ x,
                                                 const float* __restrict__ W) {
    __shared__ float W1s[OC][65];
    __shared__ float Wds[OC][65];
    __shared__ float xs[16][CH + 1];
    int tid = threadIdx.x;
    for (int t = tid; t < OC * CH; t += 256) {
        int o = t >> 6, c = t & 63;
        float w1 = W[o * 128 + c];
        float w2 = W[o * 128 + 64 + c];
        W1s[o][c] = w1;
        Wds[o][c] = w2 - w1;
    }
    int p16 = blockIdx.x * 16;
    int b = p16 >> 12, n0 = p16 & (NPTS - 1);
    for (int t = tid; t < 16 * CH; t += 256) {
        int c = t >> 4, p = t & 15;
        xs[p][c] = x[(size_t)b * CH * NPTS + (size_t)c * NPTS + n0 + p];
    }
    __syncthreads();
    int o = tid & 63, pg = tid >> 6;
    float u[4] = {0.f, 0.f, 0.f, 0.f}, v[4] = {0.f, 0.f, 0.f, 0.f};
#pragma unroll
    for (int c = 0; c < CH; c++) {
        float w1 = W1s[o][c], wd = Wds[o][c];
#pragma unroll
        for (int pp = 0; pp < 4; pp++) {
            float xv = xs[pg * 4 + pp][c];
            u[pp] = fmaf(w1, xv, u[pp]);
            v[pp] = fmaf(wd, xv, v[pp]);
        }
    }
#pragma unroll
    for (int pp = 0; pp < 4; pp++) {
        int p = pg * 4 + pp;
        size_t base = (size_t)(p16 + p) * OC + o;
        g_u[base] = u[pp];
        g_v[base] = v[pp];
        g_xt[(size_t)(p16 + p) * CH + o] = xs[p][o];
    }
}

// ---------------- fused fp16 distance MMA + register-side top-20 ------------
__global__ void __launch_bounds__(256, 2) fused_knn(const float* __restrict__ x) {
    extern __shared__ float smf[];
    uint32_t* smu = (uint32_t*)smf;

    int tid = threadIdx.x;
    int w = tid >> 5, lane = tid & 31;
    int t4 = lane & 3;
    int b = blockIdx.y, n0 = blockIdx.x << 7;

    // hsq preload (whole batch)
    for (int t = tid; t < NPTS; t += 256) smf[SM_HSQ + t] = 0.5f * g_sq[(b << 12) + t];
    // list init: encoded(-FLT_MAX) so the decoded threshold is a real float
    {
        uint32_t* lb = smu + SM_LIST + tid;
#pragma unroll
        for (int e = 0; e < 40; e++) lb[e << 8] = ENC_NEGMAX;
    }
    // A fragments (16 rows per warp) from pre-pack
    uint32_t Afr[4][4];
    {
        int wt = blockIdx.x * 8 + w;
#pragma unroll
        for (int ks = 0; ks < 4; ks++) {
            uint4 a = __ldg(&g_ap[((b * 256 + wt) * 4 + ks) * 32 + lane]);
            Afr[ks][0] = a.x; Afr[ks][1] = a.y; Afr[ks][2] = a.z; Afr[ks][3] = a.w;
        }
    }
    __syncthreads();

    uint32_t* lb0 = smu + SM_LIST + tid;
    uint32_t* lb1 = lb0 + 20 * 256;
    float worst0 = -FLT_MAX, worst1 = -FLT_MAX;
    int wp0 = 0, wp1 = 0;

    for (int mt = 0; mt < 32; mt++) {
        const uint2* bp = g_bp + (size_t)((b * 512 + (mt << 4)) * 4) * 32 + lane;
#pragma unroll 4
        for (int ct = 0; ct < 16; ct++) {
            uint2 b0 = __ldg(bp + (ct * 4 + 0) * 32);
            uint2 b1 = __ldg(bp + (ct * 4 + 1) * 32);
            uint2 b2 = __ldg(bp + (ct * 4 + 2) * 32);
            uint2 b3 = __ldg(bp + (ct * 4 + 3) * 32);
            uint32_t d0 = 0u, d1 = 0u;                 // f16 accumulators
            mma_fp16a(d0, d1, Afr[0], b0.x, b0.y);
            mma_fp16a(d0, d1, Afr[1], b1.x, b1.y);
            mma_fp16a(d0, d1, Afr[2], b2.x, b2.y);
            mma_fp16a(d0, d1, Afr[3], b3.x, b3.y);

            int m = (mt << 7) + (ct << 3) + 2 * t4;
            float2 hs = *(const float2*)(smf + SM_HSQ + m);
            float2 f01 = __half22float2(*reinterpret_cast<__half2*>(&d0));
            float2 f23 = __half22float2(*reinterpret_cast<__half2*>(&d1));
            float k0 = f01.x - hs.x, k1 = f01.y - hs.y;    // row r0
            float k2 = f23.x - hs.x, k3 = f23.y - hs.y;    // row r1
            if (k0 > worst0) ins20(lb0, enc_key(k0, m),     worst0, wp0);
            if (k1 > worst0) ins20(lb0, enc_key(k1, m + 1), worst0, wp0);
            if (k2 > worst1) ins20(lb1, enc_key(k2, m),     worst1, wp1);
            if (k3 > worst1) ins20(lb1, enc_key(k3, m + 1), worst1, wp1);
        }
    }
    __syncthreads();

    // merge 4 x top-20 -> top-32 candidates per row (owner thread per row)
    if (tid < 128) {
        int w2 = tid >> 4, gg = tid & 15;
        uint32_t* lst = smu + SM_LIST + ((gg < 8) ? 0 : 20 * 256) + w2 * 32 + ((gg & 7) << 2);
        uint32_t* scr = smu + SM_HSQ + tid * 33;   // reuse hsq region, pitch 33
#pragma unroll
        for (int s = 0; s < 32; s++) scr[s] = 0u;
        uint32_t wE = 0u; int wp = 0;
        for (int q = 0; q < 4; q++) {
#pragma unroll
            for (int e = 0; e < 20; e++) {
                uint32_t v = lst[(e << 8) + q];
                if (v > wE) {
                    scr[wp] = v;
                    uint32_t mn = scr[0]; int p = 0;
#pragma unroll
                    for (int s2 = 1; s2 < 32; s2++) {
                        uint32_t vv = scr[s2];
                        if (vv < mn) { mn = vv; p = s2; }
                    }
                    wp = p; wE = mn;
                }
            }
        }
        int* outp = g_cand + (size_t)((b << 12) + n0 + tid) * CAND;
#pragma unroll
        for (int s = 0; s < 32; s++) outp[s] = (int)(scr[s] & 0xFFFu);
    }
}

// ---------------- exact fp32 rescore of 32 candidates -> top-20 --------------
// order-invariant downstream (max/sum over k), so a bitonic sort of the
// encoded (key, inverted-idx) picks the exact top-20 set incl. tie-break.
__global__ void __launch_bounds__(256) rescore_kernel() {
    __shared__ float rowbuf[8][CH];
    int w = threadIdx.x >> 5, lane = threadIdx.x & 31;
    int row = blockIdx.x * 8 + w;
    int b = row >> 12;

    float2 me = *(const float2*)(g_xt + (size_t)row * CH + lane * 2);
    rowbuf[w][lane * 2] = me.x;
    rowbuf[w][lane * 2 + 1] = me.y;
    __syncwarp();

    int cand = g_cand[(size_t)row * CAND + lane] & (NPTS - 1);
    const float4* cp = (const float4*)(g_xt + ((size_t)(b << 12) + cand) * CH);
    float a0 = 0.f, a1 = 0.f, a2 = 0.f, a3 = 0.f;
#pragma unroll
    for (int i = 0; i < 16; i += 4) {
        float4 v0 = cp[i + 0], v1 = cp[i + 1], v2 = cp[i + 2], v3 = cp[i + 3];
        a0 = fmaf(v0.x, rowbuf[w][4 * i + 0],  a0);
        a0 = fmaf(v0.y, rowbuf[w][4 * i + 1],  a0);
        a0 = fmaf(v0.z, rowbuf[w][4 * i + 2],  a0);
        a0 = fmaf(v0.w, rowbuf[w][4 * i + 3],  a0);
        a1 = fmaf(v1.x, rowbuf[w][4 * i + 4],  a1);
        a1 = fmaf(v1.y, rowbuf[w][4 * i + 5],  a1);
        a1 = fmaf(v1.z, rowbuf[w][4 * i + 6],  a1);
        a1 = fmaf(v1.w, rowbuf[w][4 * i + 7],  a1);
        a2 = fmaf(v2.x, rowbuf[w][4 * i + 8],  a2);
        a2 = fmaf(v2.y, rowbuf[w][4 * i + 9],  a2);
        a2 = fmaf(v2.z, rowbuf[w][4 * i + 10], a2);
        a2 = fmaf(v2.w, rowbuf[w][4 * i + 11], a2);
        a3 = fmaf(v3.x, rowbuf[w][4 * i + 12], a3);
        a3 = fmaf(v3.y, rowbuf[w][4 * i + 13], a3);
        a3 = fmaf(v3.z, rowbuf[w][4 * i + 14], a3);
        a3 = fmaf(v3.w, rowbuf[w][4 * i + 15], a3);
    }
    float dot = (a0 + a1) + (a2 + a3);
    float key = fmaf(2.f, dot, -g_sq[(b << 12) + cand]);

    // encode: sortable float (full 32 bits) || (4095 - idx)  -> desc = key desc, idx asc
    uint32_t su = __float_as_uint(key);
    su ^= (su & 0x80000000u) ? 0xFFFFFFFFu : 0x80000000u;
    unsigned long long e = ((unsigned long long)su << 12) | (unsigned)(4095 - cand);

    // bitonic sort, descending across lanes
#pragma unroll
    for (int k = 2; k <= 32; k <<= 1) {
#pragma unroll
        for (int j = k >> 1; j > 0; j >>= 1) {
            unsigned long long o = __shfl_xor_sync(0xffffffffu, e, j);
            bool keepMax = ((lane & j) == 0) == ((lane & k) == 0);
            e = keepMax ? (e > o ? e : o) : (e < o ? e : o);
        }
    }
    if (lane < KNN) g_idx[(size_t)row * KNN + lane] = 4095 - (int)(e & 0xFFFu);
}

// ---------------- gather u over neighbors: max/min + BN partials ------------
__global__ void __launch_bounds__(256) gather_kernel() {
    __shared__ float shS[4][OC];
    __shared__ float shQ[4][OC];
    int o = threadIdx.x & 63, p = threadIdx.x >> 6;
    int pt = blockIdx.x * 4 + p;
    int b = pt >> 12;
    const int* idxp = g_idx + (size_t)pt * KNN;
    const float* ub = g_u + ((size_t)(b << 12)) * OC;

    float mx = -FLT_MAX, mn = FLT_MAX, s = 0.f, q = 0.f;
#pragma unroll
    for (int k = 0; k < KNN; k++) {
        int j = idxp[k] & (NPTS - 1);   // safety clamp
        float uv = ub[(size_t)j * OC + o];
        mx = fmaxf(mx, uv);
        mn = fminf(mn, uv);
        s += uv;
        q = fmaf(uv, uv, q);
    }
    size_t base = (size_t)pt * OC + o;
    float vv = g_v[base];
    g_Mmax[base] = mx;
    g_Mmin[base] = mn;
    shS[p][o] = s + (float)KNN * vv;
    shQ[p][o] = q + 2.f * vv * s + (float)KNN * vv * vv;
    __syncthreads();
    if (p == 0) {
        g_partS[blockIdx.x * OC + o] = shS[0][o] + shS[1][o] + shS[2][o] + shS[3][o];
        g_partQ[blockIdx.x * OC + o] = shQ[0][o] + shQ[1][o] + shQ[2][o] + shQ[3][o];
    }
}

// ---------------- deterministic per-channel reduction ------------------------
__global__ void reduce_kernel() {
    __shared__ float sh[256];
    int o = blockIdx.x & 63;
    bool isQ = (blockIdx.x & 64) != 0;
    const float* src = isQ ? g_partQ : g_partS;
    float s = 0.f;
    for (int i = threadIdx.x; i < 8192; i += 256) s += src[(size_t)i * OC + o];
    sh[threadIdx.x] = s;
    __syncthreads();
    for (int st = 128; st > 0; st >>= 1) {
        if (threadIdx.x < st) sh[threadIdx.x] += sh[threadIdx.x + st];
        __syncthreads();
    }
    if (threadIdx.x == 0) {
        if (isQ) g_sumsq[o] = sh[0]; else g_sum[o] = sh[0];
    }
}

__global__ void finalize_kernel(const float* __restrict__ gamma,
                                const float* __restrict__ beta) {
    int o = threadIdx.x;
    float cnt = (float)((size_t)BATCH * NPTS * KNN);
    float mean = g_sum[o] / cnt;
    float var = g_sumsq[o] / cnt - mean * mean;
    float sc = gamma[o] * rsqrtf(var + BN_EPS);
    g_scale[o] = sc;
    g_shift[o] = beta[o] - mean * sc;
}

// ---------------- output: scale/shift/leaky + transpose to [B, O, N] --------
__global__ void __launch_bounds__(256) out_kernel(float* __restrict__ out) {
    __shared__ float tile[OC][33];
    int b = blockIdx.y;
    int n0 = blockIdx.x * 32;
    for (int t = threadIdx.x; t < OC * 32; t += 256) {
        int nl = t >> 6, o = t & 63;
        size_t base = ((size_t)((b << 12) + n0 + nl)) * OC + o;
        float sc = g_scale[o];
        float m = (sc >= 0.f) ? g_Mmax[base] : g_Mmin[base];
        float y = fmaf(sc, m + g_v[base], g_shift[o]);
        tile[o][nl] = (y >= 0.f) ? y : NEG_SLOPE * y;
    }
    __syncthreads();
    for (int t = threadIdx.x; t < OC * 32; t += 256) {
        int o = t >> 5, nl = t & 31;
        out[((size_t)b * OC + o) * NPTS + n0 + nl] = tile[o][nl];
    }
}

// ---------------- launch ------------------------------------------------------
extern "C" void kernel_launch(void* const* d_in, const int* in_sizes, int n_in,
                              void* d_out, int out_size) {
    const float* x     = (const float*)d_in[0];   // [8, 64, 4096]
    const float* W     = (const float*)d_in[1];   // [64, 128]
    const float* gamma = (const float*)d_in[2];   // [64]
    const float* beta  = (const float*)d_in[3];   // [64]
    float* out = (float*)d_out;                   // [8, 64, 4096]

    cudaFuncSetAttribute(fused_knn,
                         cudaFuncAttributeMaxDynamicSharedMemorySize, SMEM_BYTES);

    sq_kernel<<<NPOINTS / 256, 256>>>(x);
    apack_kernel<<<1024, 256>>>(x);
    bpack_kernel<<<2048, 256>>>(x);
    uv_kernel<<<NPOINTS / 16, 256>>>(x, W);
    fused_knn<<<dim3(NPTS / 128, BATCH), 256, SMEM_BYTES>>>(x);
    rescore_kernel<<<NPOINTS / 8, 256>>>();
    gather_kernel<<<NPOINTS / 4, 256>>>();
    reduce_kernel<<<128, 256>>>();
    finalize_kernel<<<1, 64>>>(gamma, beta);
    out_kernel<<<dim3(NPTS / 32, BATCH), 256>>>(out);
}

// round 14
// speedup vs baseline: 1.7639x; 1.0138x over previous
#include <cuda_runtime.h>
#include <cuda_fp16.h>
#include <math.h>
#include <float.h>
#include <stdint.h>

#define BATCH 8
#define CH 64
#define NPTS 4096
#define KNN 20
#define CAND 32
#define OC 64
#define NPOINTS (BATCH * NPTS)          // 32768
#define NEG_SLOPE 0.2f
#define BN_EPS 1e-5f

// ---------------- scratch (static device globals; no allocation) ------------
__device__ uint4 g_ap[BATCH * 256 * 4 * 32];            // A-frag pack (4MB)
__device__ uint2 g_bp[BATCH * 512 * 4 * 32];            // B-frag pack (4MB)
__device__ int   g_cand[NPOINTS * CAND];
__device__ int   g_idx[NPOINTS * KNN];
__device__ float g_xt[NPOINTS * CH];
__device__ float g_u[NPOINTS * OC];
__device__ float g_v[NPOINTS * OC];
__device__ float g_sq[NPOINTS];
__device__ float g_Mmax[NPOINTS * OC];
__device__ float g_Mmin[NPOINTS * OC];
__device__ float g_partS[8192 * OC];
__device__ float g_partQ[8192 * OC];
__device__ float g_sum[OC];
__device__ float g_sumsq[OC];
__device__ float g_scale[OC];
__device__ float g_shift[OC];

// ---------------- SMEM layout of fused kernel (word indices) ----------------
#define SM_HSQ   0          // 4224 words: hsq (4096) / merge scratch (128*33)
#define SM_LIST  4224       // 40 * 256 = 10240 words (per-thread top-20 x 2 rows)
#define SM_WORDS 14464
#define SMEM_BYTES (SM_WORDS * 4)   // 57856 B

// encoded value of -FLT_MAX (list init): decodes back to -FLT_MAX exactly
#define ENC_NEGMAX 0x00800000u

// ---------------- helpers -----------------------------------------------------
__device__ __forceinline__ uint32_t pack_half2(float lo, float hi) {
    uint32_t d;
    asm("cvt.rn.f16x2.f32 %0, %2, %1;" : "=r"(d) : "f"(lo), "f"(hi));
    return d;
}
// fp16-accumulator MMA: d packed as {c0,c1},{c2,c3} half2 regs
__device__ __forceinline__ void mma_fp16a(uint32_t& c0, uint32_t& c1,
                                          const uint32_t* a, uint32_t b0, uint32_t b1) {
    asm volatile(
        "mma.sync.aligned.m16n8k16.row.col.f16.f16.f16.f16 "
        "{%0,%1}, {%2,%3,%4,%5}, {%6,%7}, {%0,%1};"
        : "+r"(c0), "+r"(c1)
        : "r"(a[0]), "r"(a[1]), "r"(a[2]), "r"(a[3]), "r"(b0), "r"(b1));
}
// order-preserving float->uint, top 20 bits kept, 12-bit column index appended
__device__ __forceinline__ uint32_t enc_key(float k, int m) {
    uint32_t u = __float_as_uint(k);
    u ^= (uint32_t)(((int)u >> 31)) | 0x80000000u;
    return (u & 0xFFFFF000u) | (uint32_t)m;
}
// insert entry into per-thread SMEM list (stride 256), refresh min slot + float threshold
__device__ __forceinline__ void ins20(uint32_t* lb, uint32_t e, float& worst, int& wp) {
    lb[wp << 8] = e;
    uint32_t mn = lb[0]; int p = 0;
#pragma unroll
    for (int t = 1; t < 20; t++) {
        uint32_t v = lb[t << 8];
        if (v < mn) { mn = v; p = t; }
    }
    wp = p;
    uint32_t eb = mn & 0xFFFFF000u;
    uint32_t dm = (eb & 0x80000000u) ? 0x80000000u : 0xFFFFFFFFu;
    worst = __uint_as_float(eb ^ dm);
}

// ---------------- |x|^2 per point -------------------------------------------
__global__ void sq_kernel(const float* __restrict__ x) {
    int t = blockIdx.x * blockDim.x + threadIdx.x;
    int b = t >> 12, n = t & (NPTS - 1);
    const float* xb = x + (size_t)b * CH * NPTS + n;
    float s = 0.f;
#pragma unroll
    for (int c = 0; c < CH; c++) { float v = xb[(size_t)c * NPTS]; s = fmaf(v, v, s); }
    g_sq[t] = s;
}

// ---------------- fragment pre-pack kernels ----------------------------------
__global__ void __launch_bounds__(256) apack_kernel(const float* __restrict__ x) {
    int t = blockIdx.x * 256 + threadIdx.x;          // 0..262143
    int lane = t & 31, ks = (t >> 5) & 3, wt = (t >> 7) & 255, b = t >> 15;
    int g = lane >> 2, t4 = lane & 3;
    int r0 = (wt << 4) + g;
    int k0 = (ks << 4) + 2 * t4;
    const float* xb = x + (size_t)b * CH * NPTS;
    uint4 o;
    o.x = pack_half2(xb[(size_t)k0 * NPTS + r0],           xb[(size_t)(k0 + 1) * NPTS + r0]);
    o.y = pack_half2(xb[(size_t)k0 * NPTS + r0 + 8],       xb[(size_t)(k0 + 1) * NPTS + r0 + 8]);
    o.z = pack_half2(xb[(size_t)(k0 + 8) * NPTS + r0],     xb[(size_t)(k0 + 9) * NPTS + r0]);
    o.w = pack_half2(xb[(size_t)(k0 + 8) * NPTS + r0 + 8], xb[(size_t)(k0 + 9) * NPTS + r0 + 8]);
    g_ap[t] = o;
}
__global__ void __launch_bounds__(256) bpack_kernel(const float* __restrict__ x) {
    int t = blockIdx.x * 256 + threadIdx.x;          // 0..524287
    int lane = t & 31, ks = (t >> 5) & 3, ct = (t >> 7) & 511, b = t >> 16;
    int n = (ct << 3) + (lane >> 2);
    int k0 = (ks << 4) + 2 * (lane & 3);
    const float* xb = x + (size_t)b * CH * NPTS;
    uint2 o;
    o.x = pack_half2(xb[(size_t)k0 * NPTS + n],       xb[(size_t)(k0 + 1) * NPTS + n]);
    o.y = pack_half2(xb[(size_t)(k0 + 8) * NPTS + n], xb[(size_t)(k0 + 9) * NPTS + n]);
    g_bp[t] = o;
}

// ---------------- u = W1*x, v = (W2-W1)*x; also writes xT --------------------
// 16 points per block: 4x fewer W reloads, weights reused across 4 points/thread
__global__ void __launch_bounds__(256) uv_kernel(const float* __restrict__ x,
                                                 const float* __restrict__ W) {
    __shared__ float W1s[OC][65];
    __shared__ float Wds[OC][65];
    __shared__ float xs[16][CH + 1];
    int tid = threadIdx.x;
    for (int t = tid; t < OC * CH; t += 256) {
        int o = t >> 6, c = t & 63;
        float w1 = W[o * 128 + c];
        float w2 = W[o * 128 + 64 + c];
        W1s[o][c] = w1;
        Wds[o][c] = w2 - w1;
    }
    int p16 = blockIdx.x * 16;
    int b = p16 >> 12, n0 = p16 & (NPTS - 1);
    for (int t = tid; t < 16 * CH; t += 256) {
        int c = t >> 4, p = t & 15;
        xs[p][c] = x[(size_t)b * CH * NPTS + (size_t)c * NPTS + n0 + p];
    }
    __syncthreads();
    int o = tid & 63, pg = tid >> 6;
    float u[4] = {0.f, 0.f, 0.f, 0.f}, v[4] = {0.f, 0.f, 0.f, 0.f};
#pragma unroll
    for (int c = 0; c < CH; c++) {
        float w1 = W1s[o][c], wd = Wds[o][c];
#pragma unroll
        for (int pp = 0; pp < 4; pp++) {
            float xv = xs[pg * 4 + pp][c];
            u[pp] = fmaf(w1, xv, u[pp]);
            v[pp] = fmaf(wd, xv, v[pp]);
        }
    }
#pragma unroll
    for (int pp = 0; pp < 4; pp++) {
        int p = pg * 4 + pp;
        size_t base = (size_t)(p16 + p) * OC + o;
        g_u[base] = u[pp];
        g_v[base] = v[pp];
        g_xt[(size_t)(p16 + p) * CH + o] = xs[p][o];
    }
}

// ---------------- fused fp16 distance MMA + register-side top-20 ------------
__global__ void __launch_bounds__(256, 2) fused_knn(const float* __restrict__ x) {
    extern __shared__ float smf[];
    uint32_t* smu = (uint32_t*)smf;

    int tid = threadIdx.x;
    int w = tid >> 5, lane = tid & 31;
    int t4 = lane & 3;
    int b = blockIdx.y, n0 = blockIdx.x << 7;

    // hsq preload (whole batch)
    for (int t = tid; t < NPTS; t += 256) smf[SM_HSQ + t] = 0.5f * g_sq[(b << 12) + t];
    // list init: encoded(-FLT_MAX) so the decoded threshold is a real float
    {
        uint32_t* lb = smu + SM_LIST + tid;
#pragma unroll
        for (int e = 0; e < 40; e++) lb[e << 8] = ENC_NEGMAX;
    }
    // A fragments (16 rows per warp) from pre-pack
    uint32_t Afr[4][4];
    {
        int wt = blockIdx.x * 8 + w;
#pragma unroll
        for (int ks = 0; ks < 4; ks++) {
            uint4 a = __ldg(&g_ap[((b * 256 + wt) * 4 + ks) * 32 + lane]);
            Afr[ks][0] = a.x; Afr[ks][1] = a.y; Afr[ks][2] = a.z; Afr[ks][3] = a.w;
        }
    }
    __syncthreads();

    uint32_t* lb0 = smu + SM_LIST + tid;
    uint32_t* lb1 = lb0 + 20 * 256;
    float worst0 = -FLT_MAX, worst1 = -FLT_MAX;
    int wp0 = 0, wp1 = 0;

    for (int mt = 0; mt < 32; mt++) {
        const uint2* bp = g_bp + (size_t)((b * 512 + (mt << 4)) * 4) * 32 + lane;
#pragma unroll 4
        for (int ct = 0; ct < 16; ct++) {
            uint2 b0 = __ldg(bp + (ct * 4 + 0) * 32);
            uint2 b1 = __ldg(bp + (ct * 4 + 1) * 32);
            uint2 b2 = __ldg(bp + (ct * 4 + 2) * 32);
            uint2 b3 = __ldg(bp + (ct * 4 + 3) * 32);
            uint32_t d0 = 0u, d1 = 0u;                 // f16 accumulators
            mma_fp16a(d0, d1, Afr[0], b0.x, b0.y);
            mma_fp16a(d0, d1, Afr[1], b1.x, b1.y);
            mma_fp16a(d0, d1, Afr[2], b2.x, b2.y);
            mma_fp16a(d0, d1, Afr[3], b3.x, b3.y);

            int m = (mt << 7) + (ct << 3) + 2 * t4;
            float2 hs = *(const float2*)(smf + SM_HSQ + m);
            float2 f01 = __half22float2(*reinterpret_cast<__half2*>(&d0));
            float2 f23 = __half22float2(*reinterpret_cast<__half2*>(&d1));
            float k0 = f01.x - hs.x, k1 = f01.y - hs.y;    // row r0
            float k2 = f23.x - hs.x, k3 = f23.y - hs.y;    // row r1
            if (k0 > worst0) ins20(lb0, enc_key(k0, m),     worst0, wp0);
            if (k1 > worst0) ins20(lb0, enc_key(k1, m + 1), worst0, wp0);
            if (k2 > worst1) ins20(lb1, enc_key(k2, m),     worst1, wp1);
            if (k3 > worst1) ins20(lb1, enc_key(k3, m + 1), worst1, wp1);
        }
    }
    __syncthreads();

    // merge 4 x top-20 -> top-32 candidates per row (owner thread per row)
    if (tid < 128) {
        int w2 = tid >> 4, gg = tid & 15;
        uint32_t* lst = smu + SM_LIST + ((gg < 8) ? 0 : 20 * 256) + w2 * 32 + ((gg & 7) << 2);
        uint32_t* scr = smu + SM_HSQ + tid * 33;   // reuse hsq region, pitch 33
#pragma unroll
        for (int s = 0; s < 32; s++) scr[s] = 0u;
        uint32_t wE = 0u; int wp = 0;
        for (int q = 0; q < 4; q++) {
#pragma unroll
            for (int e = 0; e < 20; e++) {
                uint32_t v = lst[(e << 8) + q];
                if (v > wE) {
                    scr[wp] = v;
                    uint32_t mn = scr[0]; int p = 0;
#pragma unroll
                    for (int s2 = 1; s2 < 32; s2++) {
                        uint32_t vv = scr[s2];
                        if (vv < mn) { mn = vv; p = s2; }
                    }
                    wp = p; wE = mn;
                }
            }
        }
        int* outp = g_cand + (size_t)((b << 12) + n0 + tid) * CAND;
#pragma unroll
        for (int s = 0; s < 32; s++) outp[s] = (int)(scr[s] & 0xFFFu);
    }
}

// ---------------- exact fp32 rescore of 32 candidates -> top-20 --------------
// order-invariant downstream (max/sum over k), so a bitonic sort of the
// encoded (key, inverted-idx) picks the exact top-20 set incl. tie-break.
__global__ void __launch_bounds__(256) rescore_kernel() {
    __shared__ float rowbuf[8][CH];
    int w = threadIdx.x >> 5, lane = threadIdx.x & 31;
    int row = blockIdx.x * 8 + w;
    int b = row >> 12;

    float2 me = *(const float2*)(g_xt + (size_t)row * CH + lane * 2);
    rowbuf[w][lane * 2] = me.x;
    rowbuf[w][lane * 2 + 1] = me.y;
    __syncwarp();

    int cand = g_cand[(size_t)row * CAND + lane] & (NPTS - 1);
    const float4* cp = (const float4*)(g_xt + ((size_t)(b << 12) + cand) * CH);
    float a0 = 0.f, a1 = 0.f, a2 = 0.f, a3 = 0.f;
#pragma unroll
    for (int i = 0; i < 16; i += 4) {
        float4 v0 = cp[i + 0], v1 = cp[i + 1], v2 = cp[i + 2], v3 = cp[i + 3];
        a0 = fmaf(v0.x, rowbuf[w][4 * i + 0],  a0);
        a0 = fmaf(v0.y, rowbuf[w][4 * i + 1],  a0);
        a0 = fmaf(v0.z, rowbuf[w][4 * i + 2],  a0);
        a0 = fmaf(v0.w, rowbuf[w][4 * i + 3],  a0);
        a1 = fmaf(v1.x, rowbuf[w][4 * i + 4],  a1);
        a1 = fmaf(v1.y, rowbuf[w][4 * i + 5],  a1);
        a1 = fmaf(v1.z, rowbuf[w][4 * i + 6],  a1);
        a1 = fmaf(v1.w, rowbuf[w][4 * i + 7],  a1);
        a2 = fmaf(v2.x, rowbuf[w][4 * i + 8],  a2);
        a2 = fmaf(v2.y, rowbuf[w][4 * i + 9],  a2);
        a2 = fmaf(v2.z, rowbuf[w][4 * i + 10], a2);
        a2 = fmaf(v2.w, rowbuf[w][4 * i + 11], a2);
        a3 = fmaf(v3.x, rowbuf[w][4 * i + 12], a3);
        a3 = fmaf(v3.y, rowbuf[w][4 * i + 13], a3);
        a3 = fmaf(v3.z, rowbuf[w][4 * i + 14], a3);
        a3 = fmaf(v3.w, rowbuf[w][4 * i + 15], a3);
    }
    float dot = (a0 + a1) + (a2 + a3);
    float key = fmaf(2.f, dot, -g_sq[(b << 12) + cand]);

    // encode: sortable float (full 32 bits) || (4095 - idx)  -> desc = key desc, idx asc
    uint32_t su = __float_as_uint(key);
    su ^= (su & 0x80000000u) ? 0xFFFFFFFFu : 0x80000000u;
    unsigned long long e = ((unsigned long long)su << 12) | (unsigned)(4095 - cand);

    // bitonic sort, descending across lanes
#pragma unroll
    for (int k = 2; k <= 32; k <<= 1) {
#pragma unroll
        for (int j = k >> 1; j > 0; j >>= 1) {
            unsigned long long o = __shfl_xor_sync(0xffffffffu, e, j);
            bool keepMax = ((lane & j) == 0) == ((lane & k) == 0);
            e = keepMax ? (e > o ? e : o) : (e < o ? e : o);
        }
    }
    if (lane < KNN) g_idx[(size_t)row * KNN + lane] = 4095 - (int)(e & 0xFFFu);
}

// ---------------- gather u over neighbors: max/min + BN partials ------------
__global__ void __launch_bounds__(256) gather_kernel() {
    __shared__ float shS[4][OC];
    __shared__ float shQ[4][OC];
    int o = threadIdx.x & 63, p = threadIdx.x >> 6;
    int pt = blockIdx.x * 4 + p;
    int b = pt >> 12;
    const int* idxp = g_idx + (size_t)pt * KNN;
    const float* ub = g_u + ((size_t)(b << 12)) * OC;

    float mx = -FLT_MAX, mn = FLT_MAX, s = 0.f, q = 0.f;
#pragma unroll
    for (int k = 0; k < KNN; k++) {
        int j = idxp[k] & (NPTS - 1);   // safety clamp
        float uv = ub[(size_t)j * OC + o];
        mx = fmaxf(mx, uv);
        mn = fminf(mn, uv);
        s += uv;
        q = fmaf(uv, uv, q);
    }
    size_t base = (size_t)pt * OC + o;
    float vv = g_v[base];
    g_Mmax[base] = mx;
    g_Mmin[base] = mn;
    shS[p][o] = s + (float)KNN * vv;
    shQ[p][o] = q + 2.f * vv * s + (float)KNN * vv * vv;
    __syncthreads();
    if (p == 0) {
        g_partS[blockIdx.x * OC + o] = shS[0][o] + shS[1][o] + shS[2][o] + shS[3][o];
        g_partQ[blockIdx.x * OC + o] = shQ[0][o] + shQ[1][o] + shQ[2][o] + shQ[3][o];
    }
}

// ---------------- deterministic per-channel reduction ------------------------
__global__ void reduce_kernel() {
    __shared__ float sh[256];
    int o = blockIdx.x & 63;
    bool isQ = (blockIdx.x & 64) != 0;
    const float* src = isQ ? g_partQ : g_partS;
    float s = 0.f;
    for (int i = threadIdx.x; i < 8192; i += 256) s += src[(size_t)i * OC + o];
    sh[threadIdx.x] = s;
    __syncthreads();
    for (int st = 128; st > 0; st >>= 1) {
        if (threadIdx.x < st) sh[threadIdx.x] += sh[threadIdx.x + st];
        __syncthreads();
    }
    if (threadIdx.x == 0) {
        if (isQ) g_sumsq[o] = sh[0]; else g_sum[o] = sh[0];
    }
}

__global__ void finalize_kernel(const float* __restrict__ gamma,
                                const float* __restrict__ beta) {
    int o = threadIdx.x;
    float cnt = (float)((size_t)BATCH * NPTS * KNN);
    float mean = g_sum[o] / cnt;
    float var = g_sumsq[o] / cnt - mean * mean;
    float sc = gamma[o] * rsqrtf(var + BN_EPS);
    g_scale[o] = sc;
    g_shift[o] = beta[o] - mean * sc;
}

// ---------------- output: scale/shift/leaky + transpose to [B, O, N] --------
__global__ void __launch_bounds__(256) out_kernel(float* __restrict__ out) {
    __shared__ float tile[OC][33];
    int b = blockIdx.y;
    int n0 = blockIdx.x * 32;
    for (int t = threadIdx.x; t < OC * 32; t += 256) {
        int nl = t >> 6, o = t & 63;
        size_t base = ((size_t)((b << 12) + n0 + nl)) * OC + o;
        float sc = g_scale[o];
        float m = (sc >= 0.f) ? g_Mmax[base] : g_Mmin[base];
        float y = fmaf(sc, m + g_v[base], g_shift[o]);
        tile[o][nl] = (y >= 0.f) ? y : NEG_SLOPE * y;
    }
    __syncthreads();
    for (int t = threadIdx.x; t < OC * 32; t += 256) {
        int o = t >> 5, nl = t & 31;
        out[((size_t)b * OC + o) * NPTS + n0 + nl] = tile[o][nl];
    }
}

// ---------------- launch ------------------------------------------------------
extern "C" void kernel_launch(void* const* d_in, const int* in_sizes, int n_in,
                              void* d_out, int out_size) {
    const float* x     = (const float*)d_in[0];   // [8, 64, 4096]
    const float* W     = (const float*)d_in[1];   // [64, 128]
    const float* gamma = (const float*)d_in[2];   // [64]
    const float* beta  = (const float*)d_in[3];   // [64]
    float* out = (float*)d_out;                   // [8, 64, 4096]

    cudaFuncSetAttribute(fused_knn,
                         cudaFuncAttributeMaxDynamicSharedMemorySize, SMEM_BYTES);

    sq_kernel<<<NPOINTS / 256, 256>>>(x);
    apack_kernel<<<1024, 256>>>(x);
    bpack_kernel<<<2048, 256>>>(x);
    uv_kernel<<<NPOINTS / 16, 256>>>(x, W);
    fused_knn<<<dim3(NPTS / 128, BATCH), 256, SMEM_BYTES>>>(x);
    rescore_kernel<<<NPOINTS / 8, 256>>>();
    gather_kernel<<<NPOINTS / 4, 256>>>();
    reduce_kernel<<<128, 256>>>();
    finalize_kernel<<<1, 64>>>(gamma, beta);
    out_kernel<<<dim3(NPTS / 32, BATCH), 256>>>(out);
}